// round 9
// baseline (speedup 1.0000x reference)
#include <cuda_runtime.h>

// Pyramid Givens circuit, n = m = 512, B = 256.
// Layer t in [0,1021): gates (i,i+1) for i ≡ t (mod 2), 0 <= i <= min(t, 1020-t).
// theta index: q=(t+i)/2, tidx = q(q+1)/2 + q - i.  Gate: a'=c*a+s*b ; b'=c*b-s*a.
//
// Lane L owns wires [8L,8L+7] (half h=0) and [256+8L,256+8L+7] (h=1), packed
// P[k]=(v_{w+k}, v_{w+k+4}), w=256h+8L. Active gates form a wire-PREFIX
// [0, min(t,1020-t)+1], so the upper half is active only for t in [255,765]:
// its rotps/LDS/shuffles are skipped by a warp-uniform branch elsewhere.
// Seam (255,256): lower lane31 gets v256 by warp broadcast; upper lane0
// recomputes v256 redundantly via its left-gate entry. No barriers.

#define N_WIRES   512
#define CHUNK_L   12                   // layers per bulk-copy chunk (6 stages)
#define NCHUNK    86                   // 86*12 = 1032 layers (>=1021; tail identity)
#define T_PAD     (NCHUNK * CHUNK_L)   // 1032
#define LAYER_B   2560                 // 128 rot double2 (2048) + 64 left float2 (512)
#define LEFT_OFF  2048
#define CHUNK_B   (CHUNK_L * LAYER_B)  // 30720

typedef unsigned long long ull;

// Per layer t (stride LAYER_B):
//   [0,2048): rot double2 {c2,s2}, entry at h*1024 + r*512 + lane*16
//     even t: r=0 gates (w,w+1),(w+4,w+5); r=1 gates (w+2,w+3),(w+6,w+7)
//     odd  t: r=0 gates (w+1,w+2),(w+5,w+6); r=1 gates (w+3,w+4),(w+7,w+8)
//   [2048,2560): left-gate float2 (c,s) at (h*32+lane)*8 : gate (w-1, w)
// Inactive gates stored as identity (1,0).
__device__ __align__(128) char g_tab[(size_t)T_PAD * LAYER_B];   // ~2.6 MB

__device__ __forceinline__ float2 cs_of(const float* __restrict__ th, int t, int i) {
    if (t <= 1020 && i >= 0 && i <= t && i <= 1020 - t && (((i ^ t) & 1) == 0)) {
        int q = (t + i) >> 1;
        int tidx = (q * (q + 1)) / 2 + q - i;
        float s, c;
        sincosf(th[tidx], &s, &c);
        return make_float2(c, s);
    }
    return make_float2(1.0f, 0.0f);
}

__global__ void build_cs_kernel(const float* __restrict__ thetas) {
    int t    = blockIdx.x;            // 0..T_PAD-1 (t > 1020 -> identity)
    int h    = threadIdx.x >> 6;      // 0,1
    int r    = (threadIdx.x >> 5) & 1;
    int lane = threadIdx.x & 31;
    int w    = 256 * h + 8 * lane;
    int ilo, ihi;
    if ((t & 1) == 0) { ilo = w + 2 * r;     ihi = ilo + 4; }
    else              { ilo = w + 2 * r + 1; ihi = ilo + 4; }
    float2 a = cs_of(thetas, t, ilo);
    float2 b = cs_of(thetas, t, ihi);
    char* base = g_tab + (size_t)t * LAYER_B;
    float2* dst = reinterpret_cast<float2*>(base + h * 1024 + r * 512 + lane * 16);
    dst[0] = make_float2(a.x, b.x);   // c2
    dst[1] = make_float2(a.y, b.y);   // s2
    if (r == 0) {
        float2 lf = cs_of(thetas, t, w - 1);   // identity for w==0 / parity mismatch
        *reinterpret_cast<float2*>(base + LEFT_OFF + (h * 32 + lane) * 8) = lf;
    }
}

// ---- f32x2 helpers ----
__device__ __forceinline__ ull mul2(ull a, ull b) {
    ull d; asm("mul.rn.f32x2 %0, %1, %2;" : "=l"(d) : "l"(a), "l"(b)); return d;
}
__device__ __forceinline__ ull fma2(ull a, ull b, ull c) {
    ull d; asm("fma.rn.f32x2 %0, %1, %2, %3;" : "=l"(d) : "l"(a), "l"(b), "l"(c)); return d;
}
__device__ __forceinline__ float lo_f(ull p) {
    float lo, hi; asm("mov.b64 {%0, %1}, %2;" : "=f"(lo), "=f"(hi) : "l"(p)); return lo;
}
__device__ __forceinline__ float hi_f(ull p) {
    float lo, hi; asm("mov.b64 {%0, %1}, %2;" : "=f"(lo), "=f"(hi) : "l"(p)); return hi;
}
__device__ __forceinline__ ull pk(float lo, float hi) {
    ull d; asm("mov.b64 %0, {%1, %2};" : "=l"(d) : "f"(lo), "f"(hi)); return d;
}

#define SGNMASK 0x8000000080000000ULL
#define FULLM   0xffffffffu

// Packed Givens with pre-negated sine: a' = c*a + s*b ; b' = c*b + ns*a
__device__ __forceinline__ void rotp2(ull& a, ull& b, ull c2, ull s2, ull ns2) {
    ull t1 = mul2(s2, b);
    ull na = fma2(c2, a, t1);
    ull t2 = mul2(ns2, a);
    b = fma2(c2, b, t2);
    a = na;
}

// ---- bulk-copy / mbarrier helpers ----
__device__ __forceinline__ unsigned s2u(const void* p) {
    return (unsigned)__cvta_generic_to_shared(p);
}
__device__ __forceinline__ void mbar_init(unsigned mbar, unsigned cnt) {
    asm volatile("mbarrier.init.shared.b64 [%0], %1;" :: "r"(mbar), "r"(cnt) : "memory");
}
__device__ __forceinline__ void mbar_expect_tx(unsigned mbar, unsigned bytes) {
    asm volatile("mbarrier.arrive.expect_tx.shared.b64 _, [%0], %1;"
                 :: "r"(mbar), "r"(bytes) : "memory");
}
__device__ __forceinline__ void bulk_g2s(unsigned dst, const void* src, unsigned bytes,
                                         unsigned mbar) {
    asm volatile("cp.async.bulk.shared::cluster.global.mbarrier::complete_tx::bytes "
                 "[%0], [%1], %2, [%3];"
                 :: "r"(dst), "l"(src), "r"(bytes), "r"(mbar) : "memory");
}
__device__ __forceinline__ void mbar_wait(unsigned mbar, unsigned parity) {
    unsigned done;
    asm volatile(
        "{\n\t.reg .pred p;\n\t"
        "mbarrier.try_wait.parity.acquire.cta.shared::cta.b64 p, [%1], %2;\n\t"
        "selp.b32 %0, 1, 0, p;\n\t}"
        : "=r"(done) : "r"(mbar), "r"(parity) : "memory");
    if (!done) {
        asm volatile(
            "{\n\t.reg .pred P1;\n\t"
            "WL_%=:\n\t"
            "mbarrier.try_wait.parity.acquire.cta.shared::cta.b64 P1, [%0], %1, 0x989680;\n\t"
            "@P1 bra.uni WD_%=;\n\t"
            "bra.uni WL_%=;\n\t"
            "WD_%=:\n\t}"
            :: "r"(mbar), "r"(parity) : "memory");
    }
}
__device__ __forceinline__ void fence_async_shared() {
    asm volatile("fence.proxy.async.shared::cta;" ::: "memory");
}

// Per-half stage coefficients (register ping-pong).
struct CoefH {
    ull Ec0, Es0, Ec1, Es1;
    ull Oc0, Os0, Oc1, Os1;
    float lfc, lfs;
};

__device__ __forceinline__ void load_half(CoefH& d, const char* le, int h, int lane) {
    const char* lo = le + LAYER_B;
    int ro = h * 1024 + lane * 16;
    double2 e0 = *reinterpret_cast<const double2*>(le + ro);
    double2 e1 = *reinterpret_cast<const double2*>(le + ro + 512);
    double2 o0 = *reinterpret_cast<const double2*>(lo + ro);
    double2 o1 = *reinterpret_cast<const double2*>(lo + ro + 512);
    d.Ec0 = __double_as_longlong(e0.x); d.Es0 = __double_as_longlong(e0.y);
    d.Ec1 = __double_as_longlong(e1.x); d.Es1 = __double_as_longlong(e1.y);
    d.Oc0 = __double_as_longlong(o0.x); d.Os0 = __double_as_longlong(o0.y);
    d.Oc1 = __double_as_longlong(o1.x); d.Os1 = __double_as_longlong(o1.y);
    float2 lf = *reinterpret_cast<const float2*>(lo + LEFT_OFF + (h * 32 + lane) * 8);
    d.lfc = lf.x; d.lfs = lf.y;
}

// One warp per batch row, 2 warps per CTA. cs table via single-thread
// cp.async.bulk (3 buffers, 3 chunks in flight); per-stage coefficients
// register-prefetched; upper half skipped outside its active window.
__global__ void __launch_bounds__(64, 1) apply_kernel(
    const float* __restrict__ x,
    const float* __restrict__ bias,
    float* __restrict__ out)
{
    extern __shared__ __align__(128) char sbuf[];        // 3 * CHUNK_B dynamic
    __shared__ __align__(8) unsigned long long mbar[3];

    const int tid  = threadIdx.x;
    const int lane = tid & 31;
    const int row  = blockIdx.x * 2 + (tid >> 5);

    if (tid == 0) {
        mbar_init(s2u(&mbar[0]), 1);
        mbar_init(s2u(&mbar[1]), 1);
        mbar_init(s2u(&mbar[2]), 1);
    }

    // Load both halves of the row. L[k]=(v_{8L+k}, v_{8L+k+4}); U same at +256.
    ull L[4], U[4];
    {
        const float4* xl = reinterpret_cast<const float4*>(x + (size_t)row * N_WIRES + 8 * lane);
        const float4* xu = reinterpret_cast<const float4*>(x + (size_t)row * N_WIRES + 256 + 8 * lane);
        float4 a0 = xl[0], a1 = xl[1], b0 = xu[0], b1 = xu[1];
        L[0] = pk(a0.x, a1.x); L[1] = pk(a0.y, a1.y);
        L[2] = pk(a0.z, a1.z); L[3] = pk(a0.w, a1.w);
        U[0] = pk(b0.x, b1.x); U[1] = pk(b0.y, b1.y);
        U[2] = pk(b0.z, b1.z); U[3] = pk(b0.w, b1.w);
    }

    __syncthreads();    // mbar inits visible

    if (tid == 0) {
        #pragma unroll
        for (int pc = 0; pc < 3; ++pc) {
            unsigned mb = s2u(&mbar[pc]);
            mbar_expect_tx(mb, CHUNK_B);
            bulk_g2s(s2u(sbuf + pc * CHUNK_B), g_tab + (size_t)pc * CHUNK_B, CHUNK_B, mb);
        }
    }

    CoefH CL[2], CU[2];
    int rb = 0;
    #pragma unroll 1
    for (int c = 0; c < NCHUNK; ++c) {
        mbar_wait(s2u(&mbar[rb]), (unsigned)((c / 3) & 1));

        const char* cb = sbuf + rb * CHUNK_B;
        const int tc = c * CHUNK_L;
        {
            bool up0 = (tc >= 254 && tc <= 765);
            load_half(CL[0], cb, 0, lane);
            if (up0) load_half(CU[0], cb, 1, lane);
        }

        #pragma unroll
        for (int s = 0; s < CHUNK_L / 2; ++s) {
            const int t0 = tc + 2 * s;
            const bool up = (t0 >= 254 && t0 <= 765);
            if (s + 1 < CHUNK_L / 2) {
                bool upn = (t0 + 2 >= 254 && t0 + 2 <= 765);
                load_half(CL[(s + 1) & 1], cb + (2 * (s + 1)) * LAYER_B, 0, lane);
                if (upn) load_half(CU[(s + 1) & 1], cb + (2 * (s + 1)) * LAYER_B, 1, lane);
            }
            CoefH& A = CL[s & 1];
            ull nAs0 = A.Es0 ^ SGNMASK, nAs1 = A.Es1 ^ SGNMASK;
            ull nAo0 = A.Os0 ^ SGNMASK, nAo1 = A.Os1 ^ SGNMASK;

            // ---- lower even ----
            rotp2(L[0], L[1], A.Ec0, A.Es0, nAs0);
            rotp2(L[2], L[3], A.Ec1, A.Es1, nAs1);
            float pl0  = lo_f(L[0]);
            float pl15 = hi_f(L[3]);
            float vnL = __shfl_down_sync(FULLM, pl0, 1);
            float lvL = __shfl_up_sync  (FULLM, pl15, 1);
            float baseL = A.lfc * pl0;

            if (up) {
                CoefH& Bc = CU[s & 1];
                ull nBs0 = Bc.Es0 ^ SGNMASK, nBs1 = Bc.Es1 ^ SGNMASK;
                ull nBo0 = Bc.Os0 ^ SGNMASK, nBo1 = Bc.Os1 ^ SGNMASK;

                // ---- upper even ----
                rotp2(U[0], U[1], Bc.Ec0, Bc.Es0, nBs0);
                rotp2(U[2], U[3], Bc.Ec1, Bc.Es1, nBs1);
                float pu0  = lo_f(U[0]);
                float pu15 = hi_f(U[3]);
                // seam broadcasts (post-even)
                float v256b = __shfl_sync(FULLM, pu0, 0);    // wire 256
                float v255b = __shfl_sync(FULLM, pl15, 31);  // wire 255
                float vnU = __shfl_down_sync(FULLM, pu0, 1);
                float lvU = __shfl_up_sync  (FULLM, pu15, 1);

                // ---- lower odd (seam-fed) ----
                if (lane == 31) vnL = v256b;
                rotp2(L[1], L[2], A.Oc0, A.Os0, nAo0);
                ull Ql = pk(hi_f(L[0]), vnL);
                rotp2(L[3], Ql, A.Oc1, A.Os1, nAo1);
                float nv0 = fmaf(-A.lfs, lvL, baseL);
                L[0] = pk(nv0, lo_f(Ql));

                // ---- upper odd ----
                if (lane == 0) lvU = v255b;
                if (lane == 31) vnU = 0.0f;   // gate (511,512) identity
                rotp2(U[1], U[2], Bc.Oc0, Bc.Os0, nBo0);
                ull Qu = pk(hi_f(U[0]), vnU);
                rotp2(U[3], Qu, Bc.Oc1, Bc.Os1, nBo1);
                float nu0 = fmaf(-Bc.lfs, lvU, Bc.lfc * pu0);
                U[0] = pk(nu0, lo_f(Qu));
            } else {
                // ---- lower odd only (gate (255,256) inactive -> vnL value unused
                //      at lane 31 because table entry is identity; keep shfl result) ----
                if (lane == 31) vnL = 0.0f;
                rotp2(L[1], L[2], A.Oc0, A.Os0, nAo0);
                ull Ql = pk(hi_f(L[0]), vnL);
                rotp2(L[3], Ql, A.Oc1, A.Os1, nAo1);
                float nv0 = fmaf(-A.lfs, lvL, baseL);
                L[0] = pk(nv0, lo_f(Ql));
            }
        }

        __syncthreads();   // both warps done reading buffer rb
        if (tid == 0 && c + 3 < NCHUNK) {
            fence_async_shared();
            unsigned mb = s2u(&mbar[rb]);
            mbar_expect_tx(mb, CHUNK_B);
            bulk_g2s(s2u(sbuf + rb * CHUNK_B), g_tab + (size_t)(c + 3) * CHUNK_B, CHUNK_B, mb);
        }

        rb = (rb == 2) ? 0 : rb + 1;
    }

    // store + bias: wires 8L+k <- lo(L[k]), 8L+4+k <- hi(L[k]); upper at +256
    {
        const float* bl = bias + 8 * lane;
        float* ol = out + (size_t)row * N_WIRES + 8 * lane;
        float4 bb0 = *reinterpret_cast<const float4*>(bl);
        float4 bb1 = *reinterpret_cast<const float4*>(bl + 4);
        float4 bb2 = *reinterpret_cast<const float4*>(bl + 256);
        float4 bb3 = *reinterpret_cast<const float4*>(bl + 260);
        float4 o0, o1, o2, o3;
        o0.x = lo_f(L[0]) + bb0.x; o0.y = lo_f(L[1]) + bb0.y;
        o0.z = lo_f(L[2]) + bb0.z; o0.w = lo_f(L[3]) + bb0.w;
        o1.x = hi_f(L[0]) + bb1.x; o1.y = hi_f(L[1]) + bb1.y;
        o1.z = hi_f(L[2]) + bb1.z; o1.w = hi_f(L[3]) + bb1.w;
        o2.x = lo_f(U[0]) + bb2.x; o2.y = lo_f(U[1]) + bb2.y;
        o2.z = lo_f(U[2]) + bb2.z; o2.w = lo_f(U[3]) + bb2.w;
        o3.x = hi_f(U[0]) + bb3.x; o3.y = hi_f(U[1]) + bb3.y;
        o3.z = hi_f(U[2]) + bb3.z; o3.w = hi_f(U[3]) + bb3.w;
        *reinterpret_cast<float4*>(ol)       = o0;
        *reinterpret_cast<float4*>(ol + 4)   = o1;
        *reinterpret_cast<float4*>(ol + 256) = o2;
        *reinterpret_cast<float4*>(ol + 260) = o3;
    }
}

extern "C" void kernel_launch(void* const* d_in, const int* in_sizes, int n_in,
                              void* d_out, int out_size) {
    const float* x      = (const float*)d_in[0];
    const float* thetas = (const float*)d_in[1];
    const float* bias   = (const float*)d_in[2];
    float* out = (float*)d_out;

    build_cs_kernel<<<T_PAD, 128>>>(thetas);

    cudaFuncSetAttribute(apply_kernel,
                         cudaFuncAttributeMaxDynamicSharedMemorySize, 3 * CHUNK_B);

    int B = in_sizes[0] / N_WIRES;   // 256
    apply_kernel<<<B / 2, 64, 3 * CHUNK_B>>>(x, bias, out);
}

// round 10
// speedup vs baseline: 1.4644x; 1.4644x over previous
#include <cuda_runtime.h>

// Pyramid Givens circuit, n = m = 512, B = 256.
// Layer t in [0,1021): gates (i,i+1) for i ≡ t (mod 2), 0 <= i <= min(t, 1020-t).
// theta index: q=(t+i)/2, tidx = q(q+1)/2 + q - i.  Gate: a'=c*a+s*b ; b'=c*b-s*a.
//
// Lane L owns wires [8L,8L+7] (half h=0) and [256+8L,256+8L+7] (h=1), packed
// as (v_{w+k}, v_{w+k+4}), w=256h+8L. Active gates form a wire-prefix
// [0, min(t,1020-t)+1]: the upper half is only active for t in [255,765].
// Chunks (12 layers) are phase-split: chunks 21..63 run a both-halves body,
// all others a lower-only body — straight-line code, branch 1x per chunk.
// Seam (255,256): one shfl_xor(31) exchange + redundant left-gate recompute.

#define N_WIRES   512
#define CHUNK_L   12                   // layers per bulk-copy chunk (6 stages)
#define NCHUNK    86                   // 86*12 = 1032 layers (>=1021; tail identity)
#define T_PAD     (NCHUNK * CHUNK_L)   // 1032
#define LAYER_B   2560                 // 128 rot double2 (2048) + 64 left float2 (512)
#define LEFT_OFF  2048
#define CHUNK_B   (CHUNK_L * LAYER_B)  // 30720
#define MID_LO    21                   // first both-halves chunk (t=252)
#define MID_HI    63                   // last  both-halves chunk (t=767)

typedef unsigned long long ull;

// Per layer t (stride LAYER_B):
//   [0,2048): rot double2 {c2,s2}, entry at h*1024 + r*512 + lane*16
//     even t: r=0 gates (w,w+1),(w+4,w+5); r=1 gates (w+2,w+3),(w+6,w+7)
//     odd  t: r=0 gates (w+1,w+2),(w+5,w+6); r=1 gates (w+3,w+4),(w+7,w+8)
//   [2048,2560): left-gate float2 (c, -s) at (h*32+lane)*8 : gate (w-1, w)
// Inactive gates stored as identity (1, 0 / -0).
__device__ __align__(128) char g_tab[(size_t)T_PAD * LAYER_B];   // ~2.6 MB

__device__ __forceinline__ float2 cs_of(const float* __restrict__ th, int t, int i) {
    if (t <= 1020 && i >= 0 && i <= t && i <= 1020 - t && (((i ^ t) & 1) == 0)) {
        int q = (t + i) >> 1;
        int tidx = (q * (q + 1)) / 2 + q - i;
        float s, c;
        sincosf(th[tidx], &s, &c);
        return make_float2(c, s);
    }
    return make_float2(1.0f, 0.0f);
}

__global__ void build_cs_kernel(const float* __restrict__ thetas) {
    int t    = blockIdx.x;            // 0..T_PAD-1 (t > 1020 -> identity)
    int h    = threadIdx.x >> 6;      // 0,1
    int r    = (threadIdx.x >> 5) & 1;
    int lane = threadIdx.x & 31;
    int w    = 256 * h + 8 * lane;
    int ilo, ihi;
    if ((t & 1) == 0) { ilo = w + 2 * r;     ihi = ilo + 4; }
    else              { ilo = w + 2 * r + 1; ihi = ilo + 4; }
    float2 a = cs_of(thetas, t, ilo);
    float2 b = cs_of(thetas, t, ihi);
    char* base = g_tab + (size_t)t * LAYER_B;
    float2* dst = reinterpret_cast<float2*>(base + h * 1024 + r * 512 + lane * 16);
    dst[0] = make_float2(a.x, b.x);   // c2
    dst[1] = make_float2(a.y, b.y);   // s2
    if (r == 0) {
        float2 lf = cs_of(thetas, t, w - 1);   // identity for w==0 / parity mismatch
        *reinterpret_cast<float2*>(base + LEFT_OFF + (h * 32 + lane) * 8)
            = make_float2(lf.x, -lf.y);        // sine pre-negated
    }
}

// ---- f32x2 helpers ----
__device__ __forceinline__ ull mul2(ull a, ull b) {
    ull d; asm("mul.rn.f32x2 %0, %1, %2;" : "=l"(d) : "l"(a), "l"(b)); return d;
}
__device__ __forceinline__ ull fma2(ull a, ull b, ull c) {
    ull d; asm("fma.rn.f32x2 %0, %1, %2, %3;" : "=l"(d) : "l"(a), "l"(b), "l"(c)); return d;
}
__device__ __forceinline__ float lo_f(ull p) {
    float lo, hi; asm("mov.b64 {%0, %1}, %2;" : "=f"(lo), "=f"(hi) : "l"(p)); return lo;
}
__device__ __forceinline__ float hi_f(ull p) {
    float lo, hi; asm("mov.b64 {%0, %1}, %2;" : "=f"(lo), "=f"(hi) : "l"(p)); return hi;
}
__device__ __forceinline__ ull pk(float lo, float hi) {
    ull d; asm("mov.b64 %0, {%1, %2};" : "=l"(d) : "f"(lo), "f"(hi)); return d;
}

#define SGNMASK 0x8000000080000000ULL
#define FULLM   0xffffffffu

// Packed Givens with pre-negated sine: a' = c*a + s*b ; b' = c*b + ns*a
__device__ __forceinline__ void rotp2(ull& a, ull& b, ull c2, ull s2, ull ns2) {
    ull t1 = mul2(s2, b);
    ull na = fma2(c2, a, t1);
    ull t2 = mul2(ns2, a);
    b = fma2(c2, b, t2);
    a = na;
}

// ---- bulk-copy / mbarrier helpers ----
__device__ __forceinline__ unsigned s2u(const void* p) {
    return (unsigned)__cvta_generic_to_shared(p);
}
__device__ __forceinline__ void mbar_init(unsigned mbar, unsigned cnt) {
    asm volatile("mbarrier.init.shared.b64 [%0], %1;" :: "r"(mbar), "r"(cnt) : "memory");
}
__device__ __forceinline__ void mbar_expect_tx(unsigned mbar, unsigned bytes) {
    asm volatile("mbarrier.arrive.expect_tx.shared.b64 _, [%0], %1;"
                 :: "r"(mbar), "r"(bytes) : "memory");
}
__device__ __forceinline__ void bulk_g2s(unsigned dst, const void* src, unsigned bytes,
                                         unsigned mbar) {
    asm volatile("cp.async.bulk.shared::cluster.global.mbarrier::complete_tx::bytes "
                 "[%0], [%1], %2, [%3];"
                 :: "r"(dst), "l"(src), "r"(bytes), "r"(mbar) : "memory");
}
__device__ __forceinline__ void mbar_wait(unsigned mbar, unsigned parity) {
    unsigned done;
    asm volatile(
        "{\n\t.reg .pred p;\n\t"
        "mbarrier.try_wait.parity.acquire.cta.shared::cta.b64 p, [%1], %2;\n\t"
        "selp.b32 %0, 1, 0, p;\n\t}"
        : "=r"(done) : "r"(mbar), "r"(parity) : "memory");
    if (!done) {
        asm volatile(
            "{\n\t.reg .pred P1;\n\t"
            "WL_%=:\n\t"
            "mbarrier.try_wait.parity.acquire.cta.shared::cta.b64 P1, [%0], %1, 0x989680;\n\t"
            "@P1 bra.uni WD_%=;\n\t"
            "bra.uni WL_%=;\n\t"
            "WD_%=:\n\t}"
            :: "r"(mbar), "r"(parity) : "memory");
    }
}
__device__ __forceinline__ void fence_async_shared() {
    asm volatile("fence.proxy.async.shared::cta;" ::: "memory");
}

// Per-half stage coefficients (register ping-pong).
struct CoefH {
    ull Ec0, Es0, Ec1, Es1;
    ull Oc0, Os0, Oc1, Os1;
    float lfc, lfs;     // lfs pre-negated
};

__device__ __forceinline__ void load_half(CoefH& d, const char* le, int h, int lane) {
    const char* lo = le + LAYER_B;
    int ro = h * 1024 + lane * 16;
    double2 e0 = *reinterpret_cast<const double2*>(le + ro);
    double2 e1 = *reinterpret_cast<const double2*>(le + ro + 512);
    double2 o0 = *reinterpret_cast<const double2*>(lo + ro);
    double2 o1 = *reinterpret_cast<const double2*>(lo + ro + 512);
    d.Ec0 = __double_as_longlong(e0.x); d.Es0 = __double_as_longlong(e0.y);
    d.Ec1 = __double_as_longlong(e1.x); d.Es1 = __double_as_longlong(e1.y);
    d.Oc0 = __double_as_longlong(o0.x); d.Os0 = __double_as_longlong(o0.y);
    d.Oc1 = __double_as_longlong(o1.x); d.Os1 = __double_as_longlong(o1.y);
    float2 lf = *reinterpret_cast<const float2*>(lo + LEFT_OFF + (h * 32 + lane) * 8);
    d.lfc = lf.x; d.lfs = lf.y;
}

// Lower-half two-layer stage (gate (255,256) guaranteed identity here).
__device__ __forceinline__ void stage_lower(ull* L, CoefH& A, int lane) {
    ull nAs0 = A.Es0 ^ SGNMASK, nAs1 = A.Es1 ^ SGNMASK;
    ull nAo0 = A.Os0 ^ SGNMASK, nAo1 = A.Os1 ^ SGNMASK;
    rotp2(L[0], L[1], A.Ec0, A.Es0, nAs0);
    rotp2(L[2], L[3], A.Ec1, A.Es1, nAs1);
    float pl0  = lo_f(L[0]);
    float pl15 = hi_f(L[3]);
    float vnL = __shfl_down_sync(FULLM, pl0, 1);     // lane31 value unused (identity)
    float lvL = __shfl_up_sync  (FULLM, pl15, 1);
    float baseL = A.lfc * pl0;
    rotp2(L[1], L[2], A.Oc0, A.Os0, nAo0);
    ull Ql = pk(hi_f(L[0]), vnL);
    rotp2(L[3], Ql, A.Oc1, A.Os1, nAo1);
    float nv0 = fmaf(A.lfs, lvL, baseL);             // lfs pre-negated
    L[0] = pk(nv0, lo_f(Ql));
}

// Both-halves two-layer stage with seam exchange.
__device__ __forceinline__ void stage_both(ull* L, ull* U, CoefH& A, CoefH& Bc, int lane) {
    ull nAs0 = A.Es0 ^ SGNMASK, nAs1 = A.Es1 ^ SGNMASK;
    ull nAo0 = A.Os0 ^ SGNMASK, nAo1 = A.Os1 ^ SGNMASK;
    ull nBs0 = Bc.Es0 ^ SGNMASK, nBs1 = Bc.Es1 ^ SGNMASK;
    ull nBo0 = Bc.Os0 ^ SGNMASK, nBo1 = Bc.Os1 ^ SGNMASK;

    // ---- even layers ----
    rotp2(L[0], L[1], A.Ec0, A.Es0, nAs0);
    rotp2(L[2], L[3], A.Ec1, A.Es1, nAs1);
    rotp2(U[0], U[1], Bc.Ec0, Bc.Es0, nBs0);
    rotp2(U[2], U[3], Bc.Ec1, Bc.Es1, nBs1);
    float pl0  = lo_f(L[0]);
    float pl15 = hi_f(L[3]);
    float pu0  = lo_f(U[0]);
    float pu15 = hi_f(U[3]);

    // neighbor + seam exchange (all post-even)
    float vnL = __shfl_down_sync(FULLM, pl0, 1);
    float lvL = __shfl_up_sync  (FULLM, pl15, 1);
    float vnU = __shfl_down_sync(FULLM, pu0, 1);
    float lvU = __shfl_up_sync  (FULLM, pu15, 1);
    float sx  = (lane == 0) ? pu0 : pl15;
    float ex  = __shfl_xor_sync(FULLM, sx, 31);   // lane31 <- v256, lane0 <- v255
    if (lane == 31) { vnL = ex; vnU = 0.0f; }     // gate (511,512) identity
    if (lane == 0)  { lvU = ex; }

    // ---- odd layers ----
    rotp2(L[1], L[2], A.Oc0, A.Os0, nAo0);
    ull Ql = pk(hi_f(L[0]), vnL);
    rotp2(L[3], Ql, A.Oc1, A.Os1, nAo1);
    float nv0 = fmaf(A.lfs, lvL, A.lfc * pl0);
    L[0] = pk(nv0, lo_f(Ql));

    rotp2(U[1], U[2], Bc.Oc0, Bc.Os0, nBo0);
    ull Qu = pk(hi_f(U[0]), vnU);
    rotp2(U[3], Qu, Bc.Oc1, Bc.Os1, nBo1);
    float nu0 = fmaf(Bc.lfs, lvU, Bc.lfc * pu0);
    U[0] = pk(nu0, lo_f(Qu));
}

// One warp per batch row, 2 warps per CTA. cs table via single-thread
// cp.async.bulk (3 buffers, 3 chunks in flight); coefficients register
// ping-ponged; chunks phase-split lower-only vs both-halves.
__global__ void __launch_bounds__(64, 1) apply_kernel(
    const float* __restrict__ x,
    const float* __restrict__ bias,
    float* __restrict__ out)
{
    extern __shared__ __align__(128) char sbuf[];        // 3 * CHUNK_B dynamic
    __shared__ __align__(8) unsigned long long mbar[3];

    const int tid  = threadIdx.x;
    const int lane = tid & 31;
    const int row  = blockIdx.x * 2 + (tid >> 5);

    if (tid == 0) {
        mbar_init(s2u(&mbar[0]), 1);
        mbar_init(s2u(&mbar[1]), 1);
        mbar_init(s2u(&mbar[2]), 1);
    }

    // Load both halves. L[k]=(v_{8L+k}, v_{8L+k+4}); U same at +256.
    ull L[4], U[4];
    {
        const float4* xl = reinterpret_cast<const float4*>(x + (size_t)row * N_WIRES + 8 * lane);
        const float4* xu = reinterpret_cast<const float4*>(x + (size_t)row * N_WIRES + 256 + 8 * lane);
        float4 a0 = xl[0], a1 = xl[1], b0 = xu[0], b1 = xu[1];
        L[0] = pk(a0.x, a1.x); L[1] = pk(a0.y, a1.y);
        L[2] = pk(a0.z, a1.z); L[3] = pk(a0.w, a1.w);
        U[0] = pk(b0.x, b1.x); U[1] = pk(b0.y, b1.y);
        U[2] = pk(b0.z, b1.z); U[3] = pk(b0.w, b1.w);
    }

    __syncthreads();    // mbar inits visible

    if (tid == 0) {
        #pragma unroll
        for (int pc = 0; pc < 3; ++pc) {
            unsigned mb = s2u(&mbar[pc]);
            mbar_expect_tx(mb, CHUNK_B);
            bulk_g2s(s2u(sbuf + pc * CHUNK_B), g_tab + (size_t)pc * CHUNK_B, CHUNK_B, mb);
        }
    }

    CoefH CL[2], CU[2];
    int rb = 0;
    #pragma unroll 1
    for (int c = 0; c < NCHUNK; ++c) {
        mbar_wait(s2u(&mbar[rb]), (unsigned)((c / 3) & 1));
        const char* cb = sbuf + rb * CHUNK_B;

        if (c >= MID_LO && c <= MID_HI) {
            // ---- both-halves body (straight-line, ping-pong prefetch) ----
            load_half(CL[0], cb, 0, lane);
            load_half(CU[0], cb, 1, lane);
            #pragma unroll
            for (int s = 0; s < CHUNK_L / 2; ++s) {
                if (s + 1 < CHUNK_L / 2) {
                    load_half(CL[(s + 1) & 1], cb + (2 * (s + 1)) * LAYER_B, 0, lane);
                    load_half(CU[(s + 1) & 1], cb + (2 * (s + 1)) * LAYER_B, 1, lane);
                }
                stage_both(L, U, CL[s & 1], CU[s & 1], lane);
            }
        } else {
            // ---- lower-only body ----
            load_half(CL[0], cb, 0, lane);
            #pragma unroll
            for (int s = 0; s < CHUNK_L / 2; ++s) {
                if (s + 1 < CHUNK_L / 2)
                    load_half(CL[(s + 1) & 1], cb + (2 * (s + 1)) * LAYER_B, 0, lane);
                stage_lower(L, CL[s & 1], lane);
            }
        }

        __syncthreads();   // both warps done reading buffer rb
        if (tid == 0 && c + 3 < NCHUNK) {
            fence_async_shared();
            unsigned mb = s2u(&mbar[rb]);
            mbar_expect_tx(mb, CHUNK_B);
            bulk_g2s(s2u(sbuf + rb * CHUNK_B), g_tab + (size_t)(c + 3) * CHUNK_B, CHUNK_B, mb);
        }

        rb = (rb == 2) ? 0 : rb + 1;
    }

    // store + bias: wires 8L+k <- lo(L[k]), 8L+4+k <- hi(L[k]); upper at +256
    {
        const float* bl = bias + 8 * lane;
        float* ol = out + (size_t)row * N_WIRES + 8 * lane;
        float4 bb0 = *reinterpret_cast<const float4*>(bl);
        float4 bb1 = *reinterpret_cast<const float4*>(bl + 4);
        float4 bb2 = *reinterpret_cast<const float4*>(bl + 256);
        float4 bb3 = *reinterpret_cast<const float4*>(bl + 260);
        float4 o0, o1, o2, o3;
        o0.x = lo_f(L[0]) + bb0.x; o0.y = lo_f(L[1]) + bb0.y;
        o0.z = lo_f(L[2]) + bb0.z; o0.w = lo_f(L[3]) + bb0.w;
        o1.x = hi_f(L[0]) + bb1.x; o1.y = hi_f(L[1]) + bb1.y;
        o1.z = hi_f(L[2]) + bb1.z; o1.w = hi_f(L[3]) + bb1.w;
        o2.x = lo_f(U[0]) + bb2.x; o2.y = lo_f(U[1]) + bb2.y;
        o2.z = lo_f(U[2]) + bb2.z; o2.w = lo_f(U[3]) + bb2.w;
        o3.x = hi_f(U[0]) + bb3.x; o3.y = hi_f(U[1]) + bb3.y;
        o3.z = hi_f(U[2]) + bb3.z; o3.w = hi_f(U[3]) + bb3.w;
        *reinterpret_cast<float4*>(ol)       = o0;
        *reinterpret_cast<float4*>(ol + 4)   = o1;
        *reinterpret_cast<float4*>(ol + 256) = o2;
        *reinterpret_cast<float4*>(ol + 260) = o3;
    }
}

extern "C" void kernel_launch(void* const* d_in, const int* in_sizes, int n_in,
                              void* d_out, int out_size) {
    const float* x      = (const float*)d_in[0];
    const float* thetas = (const float*)d_in[1];
    const float* bias   = (const float*)d_in[2];
    float* out = (float*)d_out;

    build_cs_kernel<<<T_PAD, 128>>>(thetas);

    cudaFuncSetAttribute(apply_kernel,
                         cudaFuncAttributeMaxDynamicSharedMemorySize, 3 * CHUNK_B);

    int B = in_sizes[0] / N_WIRES;   // 256
    apply_kernel<<<B / 2, 64, 3 * CHUNK_B>>>(x, bias, out);
}

// round 11
// speedup vs baseline: 1.5928x; 1.0877x over previous
#include <cuda_runtime.h>

// Pyramid Givens circuit, n = m = 512, B = 256.
// Layer t in [0,1021): gates (i,i+1) for i ≡ t (mod 2), 0 <= i <= min(t, 1020-t).
// theta index: q=(t+i)/2, tidx = q(q+1)/2 + q - i.  Gate: a'=c*a+s*b ; b'=c*b-s*a.
//
// Lane L owns wires [8L,8L+7] (half h=0) and [256+8L,256+8L+7] (h=1), packed
// as (v_{w+k}, v_{w+k+4}), w=256h+8L. Active gates form a wire-prefix
// [0, min(t,1020-t)+1]: the upper half is only active for t in [255,765].
// Chunks (24 layers) are phase-split: chunks 10..31 run a both-halves body,
// all others a lower-only body — straight-line code, branch 1x per chunk.
// Seam (255,256): one shfl_xor(31) exchange + redundant left-gate recompute.

#define N_WIRES   512
#define CHUNK_L   24                   // layers per bulk-copy chunk (12 stages)
#define NCHUNK    43                   // 43*24 = 1032 layers (>=1021; tail identity)
#define T_PAD     (NCHUNK * CHUNK_L)   // 1032
#define LAYER_B   2560                 // 128 rot double2 (2048) + 64 left float2 (512)
#define LEFT_OFF  2048
#define CHUNK_B   (CHUNK_L * LAYER_B)  // 61440
#define MID_LO    10                   // first both-halves chunk (t=240)
#define MID_HI    31                   // last  both-halves chunk (t=767)

typedef unsigned long long ull;

// Per layer t (stride LAYER_B):
//   [0,2048): rot double2 {c2,s2}, entry at h*1024 + r*512 + lane*16
//     even t: r=0 gates (w,w+1),(w+4,w+5); r=1 gates (w+2,w+3),(w+6,w+7)
//     odd  t: r=0 gates (w+1,w+2),(w+5,w+6); r=1 gates (w+3,w+4),(w+7,w+8)
//   [2048,2560): left-gate float2 (c, -s) at (h*32+lane)*8 : gate (w-1, w)
// Inactive gates stored as identity (1, 0 / -0).
__device__ __align__(128) char g_tab[(size_t)T_PAD * LAYER_B];   // ~2.6 MB

__device__ __forceinline__ float2 cs_of(const float* __restrict__ th, int t, int i) {
    if (t <= 1020 && i >= 0 && i <= t && i <= 1020 - t && (((i ^ t) & 1) == 0)) {
        int q = (t + i) >> 1;
        int tidx = (q * (q + 1)) / 2 + q - i;
        float s, c;
        sincosf(th[tidx], &s, &c);
        return make_float2(c, s);
    }
    return make_float2(1.0f, 0.0f);
}

__global__ void build_cs_kernel(const float* __restrict__ thetas) {
    int t    = blockIdx.x;            // 0..T_PAD-1 (t > 1020 -> identity)
    int h    = threadIdx.x >> 6;      // 0,1
    int r    = (threadIdx.x >> 5) & 1;
    int lane = threadIdx.x & 31;
    int w    = 256 * h + 8 * lane;
    int ilo, ihi;
    if ((t & 1) == 0) { ilo = w + 2 * r;     ihi = ilo + 4; }
    else              { ilo = w + 2 * r + 1; ihi = ilo + 4; }
    float2 a = cs_of(thetas, t, ilo);
    float2 b = cs_of(thetas, t, ihi);
    char* base = g_tab + (size_t)t * LAYER_B;
    float2* dst = reinterpret_cast<float2*>(base + h * 1024 + r * 512 + lane * 16);
    dst[0] = make_float2(a.x, b.x);   // c2
    dst[1] = make_float2(a.y, b.y);   // s2
    if (r == 0) {
        float2 lf = cs_of(thetas, t, w - 1);   // identity for w==0 / parity mismatch
        *reinterpret_cast<float2*>(base + LEFT_OFF + (h * 32 + lane) * 8)
            = make_float2(lf.x, -lf.y);        // sine pre-negated
    }
}

// ---- f32x2 helpers ----
__device__ __forceinline__ ull mul2(ull a, ull b) {
    ull d; asm("mul.rn.f32x2 %0, %1, %2;" : "=l"(d) : "l"(a), "l"(b)); return d;
}
__device__ __forceinline__ ull fma2(ull a, ull b, ull c) {
    ull d; asm("fma.rn.f32x2 %0, %1, %2, %3;" : "=l"(d) : "l"(a), "l"(b), "l"(c)); return d;
}
__device__ __forceinline__ float lo_f(ull p) {
    float lo, hi; asm("mov.b64 {%0, %1}, %2;" : "=f"(lo), "=f"(hi) : "l"(p)); return lo;
}
__device__ __forceinline__ float hi_f(ull p) {
    float lo, hi; asm("mov.b64 {%0, %1}, %2;" : "=f"(lo), "=f"(hi) : "l"(p)); return hi;
}
__device__ __forceinline__ ull pk(float lo, float hi) {
    ull d; asm("mov.b64 %0, {%1, %2};" : "=l"(d) : "f"(lo), "f"(hi)); return d;
}

#define SGNMASK 0x8000000080000000ULL
#define FULLM   0xffffffffu

// Packed Givens with pre-negated sine: a' = c*a + s*b ; b' = c*b + ns*a
__device__ __forceinline__ void rotp2(ull& a, ull& b, ull c2, ull s2, ull ns2) {
    ull t1 = mul2(s2, b);
    ull na = fma2(c2, a, t1);
    ull t2 = mul2(ns2, a);
    b = fma2(c2, b, t2);
    a = na;
}

// ---- bulk-copy / mbarrier helpers ----
__device__ __forceinline__ unsigned s2u(const void* p) {
    return (unsigned)__cvta_generic_to_shared(p);
}
__device__ __forceinline__ void mbar_init(unsigned mbar, unsigned cnt) {
    asm volatile("mbarrier.init.shared.b64 [%0], %1;" :: "r"(mbar), "r"(cnt) : "memory");
}
__device__ __forceinline__ void mbar_expect_tx(unsigned mbar, unsigned bytes) {
    asm volatile("mbarrier.arrive.expect_tx.shared.b64 _, [%0], %1;"
                 :: "r"(mbar), "r"(bytes) : "memory");
}
__device__ __forceinline__ void bulk_g2s(unsigned dst, const void* src, unsigned bytes,
                                         unsigned mbar) {
    asm volatile("cp.async.bulk.shared::cluster.global.mbarrier::complete_tx::bytes "
                 "[%0], [%1], %2, [%3];"
                 :: "r"(dst), "l"(src), "r"(bytes), "r"(mbar) : "memory");
}
__device__ __forceinline__ void mbar_wait(unsigned mbar, unsigned parity) {
    unsigned done;
    asm volatile(
        "{\n\t.reg .pred p;\n\t"
        "mbarrier.try_wait.parity.acquire.cta.shared::cta.b64 p, [%1], %2;\n\t"
        "selp.b32 %0, 1, 0, p;\n\t}"
        : "=r"(done) : "r"(mbar), "r"(parity) : "memory");
    if (!done) {
        asm volatile(
            "{\n\t.reg .pred P1;\n\t"
            "WL_%=:\n\t"
            "mbarrier.try_wait.parity.acquire.cta.shared::cta.b64 P1, [%0], %1, 0x989680;\n\t"
            "@P1 bra.uni WD_%=;\n\t"
            "bra.uni WL_%=;\n\t"
            "WD_%=:\n\t}"
            :: "r"(mbar), "r"(parity) : "memory");
    }
}
__device__ __forceinline__ void fence_async_shared() {
    asm volatile("fence.proxy.async.shared::cta;" ::: "memory");
}

// Per-half stage coefficients (register ping-pong).
struct CoefH {
    ull Ec0, Es0, Ec1, Es1;
    ull Oc0, Os0, Oc1, Os1;
    float lfc, lfs;     // lfs pre-negated
};

__device__ __forceinline__ void load_half(CoefH& d, const char* le, int h, int lane) {
    const char* lo = le + LAYER_B;
    int ro = h * 1024 + lane * 16;
    double2 e0 = *reinterpret_cast<const double2*>(le + ro);
    double2 e1 = *reinterpret_cast<const double2*>(le + ro + 512);
    double2 o0 = *reinterpret_cast<const double2*>(lo + ro);
    double2 o1 = *reinterpret_cast<const double2*>(lo + ro + 512);
    d.Ec0 = __double_as_longlong(e0.x); d.Es0 = __double_as_longlong(e0.y);
    d.Ec1 = __double_as_longlong(e1.x); d.Es1 = __double_as_longlong(e1.y);
    d.Oc0 = __double_as_longlong(o0.x); d.Os0 = __double_as_longlong(o0.y);
    d.Oc1 = __double_as_longlong(o1.x); d.Os1 = __double_as_longlong(o1.y);
    float2 lf = *reinterpret_cast<const float2*>(lo + LEFT_OFF + (h * 32 + lane) * 8);
    d.lfc = lf.x; d.lfs = lf.y;
}

// Lower-half two-layer stage (gate (255,256) guaranteed identity here;
// lane31's shuffled vn value only feeds that identity hi-gate -> junk safe).
__device__ __forceinline__ void stage_lower(ull* L, CoefH& A, int lane) {
    ull nAs0 = A.Es0 ^ SGNMASK, nAs1 = A.Es1 ^ SGNMASK;
    ull nAo0 = A.Os0 ^ SGNMASK, nAo1 = A.Os1 ^ SGNMASK;
    rotp2(L[0], L[1], A.Ec0, A.Es0, nAs0);
    rotp2(L[2], L[3], A.Ec1, A.Es1, nAs1);
    float pl0  = lo_f(L[0]);
    float pl15 = hi_f(L[3]);
    float vnL = __shfl_down_sync(FULLM, pl0, 1);
    float lvL = __shfl_up_sync  (FULLM, pl15, 1);
    float baseL = A.lfc * pl0;
    rotp2(L[1], L[2], A.Oc0, A.Os0, nAo0);
    ull Ql = pk(hi_f(L[0]), vnL);
    rotp2(L[3], Ql, A.Oc1, A.Os1, nAo1);
    float nv0 = fmaf(A.lfs, lvL, baseL);             // lfs pre-negated
    L[0] = pk(nv0, lo_f(Ql));
}

// Both-halves two-layer stage with seam exchange. (Gate (511,512) is always
// identity, so lane31's junk vnU is safe unzeroed.)
__device__ __forceinline__ void stage_both(ull* L, ull* U, CoefH& A, CoefH& Bc, int lane) {
    ull nAs0 = A.Es0 ^ SGNMASK, nAs1 = A.Es1 ^ SGNMASK;
    ull nAo0 = A.Os0 ^ SGNMASK, nAo1 = A.Os1 ^ SGNMASK;
    ull nBs0 = Bc.Es0 ^ SGNMASK, nBs1 = Bc.Es1 ^ SGNMASK;
    ull nBo0 = Bc.Os0 ^ SGNMASK, nBo1 = Bc.Os1 ^ SGNMASK;

    // ---- even layers ----
    rotp2(L[0], L[1], A.Ec0, A.Es0, nAs0);
    rotp2(L[2], L[3], A.Ec1, A.Es1, nAs1);
    rotp2(U[0], U[1], Bc.Ec0, Bc.Es0, nBs0);
    rotp2(U[2], U[3], Bc.Ec1, Bc.Es1, nBs1);
    float pl0  = lo_f(L[0]);
    float pl15 = hi_f(L[3]);
    float pu0  = lo_f(U[0]);
    float pu15 = hi_f(U[3]);

    // neighbor + seam exchange (all post-even)
    float vnL = __shfl_down_sync(FULLM, pl0, 1);
    float lvL = __shfl_up_sync  (FULLM, pl15, 1);
    float vnU = __shfl_down_sync(FULLM, pu0, 1);
    float lvU = __shfl_up_sync  (FULLM, pu15, 1);
    float sx  = (lane == 0) ? pu0 : pl15;
    float ex  = __shfl_xor_sync(FULLM, sx, 31);   // lane31 <- v256, lane0 <- v255
    if (lane == 31) { vnL = ex; }
    if (lane == 0)  { lvU = ex; }

    // ---- odd layers ----
    rotp2(L[1], L[2], A.Oc0, A.Os0, nAo0);
    ull Ql = pk(hi_f(L[0]), vnL);
    rotp2(L[3], Ql, A.Oc1, A.Os1, nAo1);
    float nv0 = fmaf(A.lfs, lvL, A.lfc * pl0);
    L[0] = pk(nv0, lo_f(Ql));

    rotp2(U[1], U[2], Bc.Oc0, Bc.Os0, nBo0);
    ull Qu = pk(hi_f(U[0]), vnU);
    rotp2(U[3], Qu, Bc.Oc1, Bc.Os1, nBo1);
    float nu0 = fmaf(Bc.lfs, lvU, Bc.lfc * pu0);
    U[0] = pk(nu0, lo_f(Qu));
}

// One warp per batch row, 2 warps per CTA. cs table via single-thread
// cp.async.bulk (3 buffers, 3 chunks in flight); coefficients register
// ping-ponged; chunks phase-split lower-only vs both-halves.
__global__ void __launch_bounds__(64, 1) apply_kernel(
    const float* __restrict__ x,
    const float* __restrict__ bias,
    float* __restrict__ out)
{
    extern __shared__ __align__(128) char sbuf[];        // 3 * CHUNK_B dynamic
    __shared__ __align__(8) unsigned long long mbar[3];

    const int tid  = threadIdx.x;
    const int lane = tid & 31;
    const int row  = blockIdx.x * 2 + (tid >> 5);

    if (tid == 0) {
        mbar_init(s2u(&mbar[0]), 1);
        mbar_init(s2u(&mbar[1]), 1);
        mbar_init(s2u(&mbar[2]), 1);
    }

    // Load both halves. L[k]=(v_{8L+k}, v_{8L+k+4}); U same at +256.
    ull L[4], U[4];
    {
        const float4* xl = reinterpret_cast<const float4*>(x + (size_t)row * N_WIRES + 8 * lane);
        const float4* xu = reinterpret_cast<const float4*>(x + (size_t)row * N_WIRES + 256 + 8 * lane);
        float4 a0 = xl[0], a1 = xl[1], b0 = xu[0], b1 = xu[1];
        L[0] = pk(a0.x, a1.x); L[1] = pk(a0.y, a1.y);
        L[2] = pk(a0.z, a1.z); L[3] = pk(a0.w, a1.w);
        U[0] = pk(b0.x, b1.x); U[1] = pk(b0.y, b1.y);
        U[2] = pk(b0.z, b1.z); U[3] = pk(b0.w, b1.w);
    }

    __syncthreads();    // mbar inits visible

    if (tid == 0) {
        #pragma unroll
        for (int pc = 0; pc < 3; ++pc) {
            unsigned mb = s2u(&mbar[pc]);
            mbar_expect_tx(mb, CHUNK_B);
            bulk_g2s(s2u(sbuf + pc * CHUNK_B), g_tab + (size_t)pc * CHUNK_B, CHUNK_B, mb);
        }
    }

    CoefH CL[2], CU[2];
    int rb = 0;
    #pragma unroll 1
    for (int c = 0; c < NCHUNK; ++c) {
        mbar_wait(s2u(&mbar[rb]), (unsigned)((c / 3) & 1));
        const char* cb = sbuf + rb * CHUNK_B;

        if (c >= MID_LO && c <= MID_HI) {
            // ---- both-halves body (straight-line, ping-pong prefetch) ----
            load_half(CL[0], cb, 0, lane);
            load_half(CU[0], cb, 1, lane);
            #pragma unroll 4
            for (int s = 0; s < CHUNK_L / 2; ++s) {
                if (s + 1 < CHUNK_L / 2) {
                    load_half(CL[(s + 1) & 1], cb + (2 * (s + 1)) * LAYER_B, 0, lane);
                    load_half(CU[(s + 1) & 1], cb + (2 * (s + 1)) * LAYER_B, 1, lane);
                }
                stage_both(L, U, CL[s & 1], CU[s & 1], lane);
            }
        } else {
            // ---- lower-only body ----
            load_half(CL[0], cb, 0, lane);
            #pragma unroll 4
            for (int s = 0; s < CHUNK_L / 2; ++s) {
                if (s + 1 < CHUNK_L / 2)
                    load_half(CL[(s + 1) & 1], cb + (2 * (s + 1)) * LAYER_B, 0, lane);
                stage_lower(L, CL[s & 1], lane);
            }
        }

        __syncthreads();   // both warps done reading buffer rb
        if (tid == 0 && c + 3 < NCHUNK) {
            fence_async_shared();
            unsigned mb = s2u(&mbar[rb]);
            mbar_expect_tx(mb, CHUNK_B);
            bulk_g2s(s2u(sbuf + rb * CHUNK_B), g_tab + (size_t)(c + 3) * CHUNK_B, CHUNK_B, mb);
        }

        rb = (rb == 2) ? 0 : rb + 1;
    }

    // store + bias: wires 8L+k <- lo(L[k]), 8L+4+k <- hi(L[k]); upper at +256
    {
        const float* bl = bias + 8 * lane;
        float* ol = out + (size_t)row * N_WIRES + 8 * lane;
        float4 bb0 = *reinterpret_cast<const float4*>(bl);
        float4 bb1 = *reinterpret_cast<const float4*>(bl + 4);
        float4 bb2 = *reinterpret_cast<const float4*>(bl + 256);
        float4 bb3 = *reinterpret_cast<const float4*>(bl + 260);
        float4 o0, o1, o2, o3;
        o0.x = lo_f(L[0]) + bb0.x; o0.y = lo_f(L[1]) + bb0.y;
        o0.z = lo_f(L[2]) + bb0.z; o0.w = lo_f(L[3]) + bb0.w;
        o1.x = hi_f(L[0]) + bb1.x; o1.y = hi_f(L[1]) + bb1.y;
        o1.z = hi_f(L[2]) + bb1.z; o1.w = hi_f(L[3]) + bb1.w;
        o2.x = lo_f(U[0]) + bb2.x; o2.y = lo_f(U[1]) + bb2.y;
        o2.z = lo_f(U[2]) + bb2.z; o2.w = lo_f(U[3]) + bb2.w;
        o3.x = hi_f(U[0]) + bb3.x; o3.y = hi_f(U[1]) + bb3.y;
        o3.z = hi_f(U[2]) + bb3.z; o3.w = hi_f(U[3]) + bb3.w;
        *reinterpret_cast<float4*>(ol)       = o0;
        *reinterpret_cast<float4*>(ol + 4)   = o1;
        *reinterpret_cast<float4*>(ol + 256) = o2;
        *reinterpret_cast<float4*>(ol + 260) = o3;
    }
}

extern "C" void kernel_launch(void* const* d_in, const int* in_sizes, int n_in,
                              void* d_out, int out_size) {
    const float* x      = (const float*)d_in[0];
    const float* thetas = (const float*)d_in[1];
    const float* bias   = (const float*)d_in[2];
    float* out = (float*)d_out;

    build_cs_kernel<<<T_PAD, 128>>>(thetas);

    cudaFuncSetAttribute(apply_kernel,
                         cudaFuncAttributeMaxDynamicSharedMemorySize, 3 * CHUNK_B);

    int B = in_sizes[0] / N_WIRES;   // 256
    apply_kernel<<<B / 2, 64, 3 * CHUNK_B>>>(x, bias, out);
}

// round 12
// speedup vs baseline: 1.6891x; 1.0605x over previous
#include <cuda_runtime.h>

// Pyramid Givens circuit, n = m = 512, B = 256.
// Layer t in [0,1021): gates (i,i+1) for i ≡ t (mod 2), 0 <= i <= min(t, 1020-t).
// theta index: q=(t+i)/2, tidx = q(q+1)/2 + q - i.  Gate: a'=c*a+s*b ; b'=c*b-s*a.
//
// Lane L owns wires [8L,8L+7] (h=0) and [256+8L,256+8L+7] (h=1), packed as
// (v_{w+k}, v_{w+k+4}). Upper half active only for t in [255,765]; chunks
// (24 layers) phase-split into both-halves / lower-only straight-line bodies.
// All smem coefficient loads: 32-bit shared base + compile-time immediate.

#define N_WIRES   512
#define CHUNK_L   24
#define NCHUNK    43                   // 43*24 = 1032 layers (tail identity)
#define T_PAD     (NCHUNK * CHUNK_L)
#define LAYER_B   2560                 // 128 rot double2 + 64 left float2
#define LEFT_OFF  2048
#define CHUNK_B   (CHUNK_L * LAYER_B)  // 61440
#define STAGE_B   (2 * LAYER_B)        // 5120
#define MID_LO    10
#define MID_HI    31

typedef unsigned long long ull;

__device__ __align__(128) char g_tab[(size_t)T_PAD * LAYER_B];   // ~2.6 MB

__device__ __forceinline__ float2 cs_of(const float* __restrict__ th, int t, int i) {
    if (t <= 1020 && i >= 0 && i <= t && i <= 1020 - t && (((i ^ t) & 1) == 0)) {
        int q = (t + i) >> 1;
        int tidx = (q * (q + 1)) / 2 + q - i;
        float s, c;
        sincosf(th[tidx], &s, &c);
        return make_float2(c, s);
    }
    return make_float2(1.0f, 0.0f);
}

__global__ void build_cs_kernel(const float* __restrict__ thetas) {
    int t    = blockIdx.x;
    int h    = threadIdx.x >> 6;
    int r    = (threadIdx.x >> 5) & 1;
    int lane = threadIdx.x & 31;
    int w    = 256 * h + 8 * lane;
    int ilo, ihi;
    if ((t & 1) == 0) { ilo = w + 2 * r;     ihi = ilo + 4; }
    else              { ilo = w + 2 * r + 1; ihi = ilo + 4; }
    float2 a = cs_of(thetas, t, ilo);
    float2 b = cs_of(thetas, t, ihi);
    char* base = g_tab + (size_t)t * LAYER_B;
    float2* dst = reinterpret_cast<float2*>(base + h * 1024 + r * 512 + lane * 16);
    dst[0] = make_float2(a.x, b.x);   // c2
    dst[1] = make_float2(a.y, b.y);   // s2
    if (r == 0) {
        float2 lf = cs_of(thetas, t, w - 1);
        *reinterpret_cast<float2*>(base + LEFT_OFF + (h * 32 + lane) * 8)
            = make_float2(lf.x, -lf.y);        // sine pre-negated
    }
}

// ---- f32x2 helpers ----
__device__ __forceinline__ ull mul2(ull a, ull b) {
    ull d; asm("mul.rn.f32x2 %0, %1, %2;" : "=l"(d) : "l"(a), "l"(b)); return d;
}
__device__ __forceinline__ ull fma2(ull a, ull b, ull c) {
    ull d; asm("fma.rn.f32x2 %0, %1, %2, %3;" : "=l"(d) : "l"(a), "l"(b), "l"(c)); return d;
}
__device__ __forceinline__ float lo_f(ull p) {
    float lo; asm("{ .reg .b32 hi_; mov.b64 {%0, hi_}, %1; }" : "=f"(lo) : "l"(p)); return lo;
}
__device__ __forceinline__ float hi_f(ull p) {
    float hi; asm("{ .reg .b32 lo_; mov.b64 {lo_, %0}, %1; }" : "=f"(hi) : "l"(p)); return hi;
}
__device__ __forceinline__ ull pk(float lo, float hi) {
    ull d; asm("mov.b64 %0, {%1, %2};" : "=l"(d) : "f"(lo), "f"(hi)); return d;
}

#define SGNMASK 0x8000000080000000ULL
#define FULLM   0xffffffffu

__device__ __forceinline__ void rotp2(ull& a, ull& b, ull c2, ull s2, ull ns2) {
    ull t1 = mul2(s2, b);
    ull na = fma2(c2, a, t1);
    ull t2 = mul2(ns2, a);
    b = fma2(c2, b, t2);
    a = na;
}

// ---- 32-bit shared loads with immediate offsets ----
template<int OFF>
__device__ __forceinline__ void lds_u64x2(unsigned base, ull& x, ull& y) {
    asm volatile("ld.shared.v2.u64 {%0, %1}, [%2+%3];"
                 : "=l"(x), "=l"(y) : "r"(base), "n"(OFF));
}
template<int OFF>
__device__ __forceinline__ void lds_f32x2(unsigned base, float& x, float& y) {
    asm volatile("ld.shared.v2.f32 {%0, %1}, [%2+%3];"
                 : "=f"(x), "=f"(y) : "r"(base), "n"(OFF));
}

// ---- bulk-copy / mbarrier helpers ----
__device__ __forceinline__ unsigned s2u(const void* p) {
    return (unsigned)__cvta_generic_to_shared(p);
}
__device__ __forceinline__ void mbar_init(unsigned mbar, unsigned cnt) {
    asm volatile("mbarrier.init.shared.b64 [%0], %1;" :: "r"(mbar), "r"(cnt) : "memory");
}
__device__ __forceinline__ void mbar_expect_tx(unsigned mbar, unsigned bytes) {
    asm volatile("mbarrier.arrive.expect_tx.shared.b64 _, [%0], %1;"
                 :: "r"(mbar), "r"(bytes) : "memory");
}
__device__ __forceinline__ void bulk_g2s(unsigned dst, const void* src, unsigned bytes,
                                         unsigned mbar) {
    asm volatile("cp.async.bulk.shared::cluster.global.mbarrier::complete_tx::bytes "
                 "[%0], [%1], %2, [%3];"
                 :: "r"(dst), "l"(src), "r"(bytes), "r"(mbar) : "memory");
}
__device__ __forceinline__ void mbar_wait(unsigned mbar, unsigned parity) {
    unsigned done;
    asm volatile(
        "{\n\t.reg .pred p;\n\t"
        "mbarrier.try_wait.parity.acquire.cta.shared::cta.b64 p, [%1], %2;\n\t"
        "selp.b32 %0, 1, 0, p;\n\t}"
        : "=r"(done) : "r"(mbar), "r"(parity) : "memory");
    if (!done) {
        asm volatile(
            "{\n\t.reg .pred P1;\n\t"
            "WL_%=:\n\t"
            "mbarrier.try_wait.parity.acquire.cta.shared::cta.b64 P1, [%0], %1, 0x989680;\n\t"
            "@P1 bra.uni WD_%=;\n\t"
            "bra.uni WL_%=;\n\t"
            "WD_%=:\n\t}"
            :: "r"(mbar), "r"(parity) : "memory");
    }
}
__device__ __forceinline__ void fence_async_shared() {
    asm volatile("fence.proxy.async.shared::cta;" ::: "memory");
}

struct CoefH {
    ull Ec0, Es0, Ec1, Es1;
    ull Oc0, Os0, Oc1, Os1;
    float lfc, lfs;     // lfs pre-negated
};

// Load coefs for (stage S, half H): all offsets compile-time immediates.
#define LDH(d, S, H) do {                                                        \
    lds_u64x2<(S)*STAGE_B + (H)*1024          >(rbase, (d).Ec0, (d).Es0);        \
    lds_u64x2<(S)*STAGE_B + (H)*1024 + 512    >(rbase, (d).Ec1, (d).Es1);        \
    lds_u64x2<(S)*STAGE_B + LAYER_B + (H)*1024      >(rbase, (d).Oc0, (d).Os0);  \
    lds_u64x2<(S)*STAGE_B + LAYER_B + (H)*1024 + 512>(rbase, (d).Oc1, (d).Os1);  \
    lds_f32x2<(S)*STAGE_B + LAYER_B + LEFT_OFF + (H)*256>(lbase, (d).lfc, (d).lfs); \
} while (0)

__device__ __forceinline__ void stage_lower(ull* L, CoefH& A, int lane) {
    ull nAs0 = A.Es0 ^ SGNMASK, nAs1 = A.Es1 ^ SGNMASK;
    ull nAo0 = A.Os0 ^ SGNMASK, nAo1 = A.Os1 ^ SGNMASK;
    rotp2(L[0], L[1], A.Ec0, A.Es0, nAs0);
    rotp2(L[2], L[3], A.Ec1, A.Es1, nAs1);
    float pl0  = lo_f(L[0]);
    float pl15 = hi_f(L[3]);
    float vnL = __shfl_down_sync(FULLM, pl0, 1);   // lane31 junk safe (identity gate)
    float lvL = __shfl_up_sync  (FULLM, pl15, 1);
    float baseL = A.lfc * pl0;
    rotp2(L[1], L[2], A.Oc0, A.Os0, nAo0);
    ull Ql = pk(hi_f(L[0]), vnL);
    rotp2(L[3], Ql, A.Oc1, A.Os1, nAo1);
    float nv0 = fmaf(A.lfs, lvL, baseL);
    L[0] = pk(nv0, lo_f(Ql));
}

__device__ __forceinline__ void stage_both(ull* L, ull* U, CoefH& A, CoefH& Bc, int lane) {
    ull nAs0 = A.Es0 ^ SGNMASK, nAs1 = A.Es1 ^ SGNMASK;
    ull nAo0 = A.Os0 ^ SGNMASK, nAo1 = A.Os1 ^ SGNMASK;
    ull nBs0 = Bc.Es0 ^ SGNMASK, nBs1 = Bc.Es1 ^ SGNMASK;
    ull nBo0 = Bc.Os0 ^ SGNMASK, nBo1 = Bc.Os1 ^ SGNMASK;

    rotp2(L[0], L[1], A.Ec0, A.Es0, nAs0);
    rotp2(L[2], L[3], A.Ec1, A.Es1, nAs1);
    rotp2(U[0], U[1], Bc.Ec0, Bc.Es0, nBs0);
    rotp2(U[2], U[3], Bc.Ec1, Bc.Es1, nBs1);
    float pl0  = lo_f(L[0]);
    float pl15 = hi_f(L[3]);
    float pu0  = lo_f(U[0]);
    float pu15 = hi_f(U[3]);

    float vnL = __shfl_down_sync(FULLM, pl0, 1);
    float lvL = __shfl_up_sync  (FULLM, pl15, 1);
    float vnU = __shfl_down_sync(FULLM, pu0, 1);   // lane31 junk safe (511/512 identity)
    float lvU = __shfl_up_sync  (FULLM, pu15, 1);
    float sx  = (lane == 0) ? pu0 : pl15;
    float ex  = __shfl_xor_sync(FULLM, sx, 31);    // lane31 <- v256, lane0 <- v255
    if (lane == 31) { vnL = ex; }
    if (lane == 0)  { lvU = ex; }

    rotp2(L[1], L[2], A.Oc0, A.Os0, nAo0);
    ull Ql = pk(hi_f(L[0]), vnL);
    rotp2(L[3], Ql, A.Oc1, A.Os1, nAo1);
    float nv0 = fmaf(A.lfs, lvL, A.lfc * pl0);
    L[0] = pk(nv0, lo_f(Ql));

    rotp2(U[1], U[2], Bc.Oc0, Bc.Os0, nBo0);
    ull Qu = pk(hi_f(U[0]), vnU);
    rotp2(U[3], Qu, Bc.Oc1, Bc.Os1, nBo1);
    float nu0 = fmaf(Bc.lfs, lvU, Bc.lfc * pu0);
    U[0] = pk(nu0, lo_f(Qu));
}

__global__ void __launch_bounds__(64, 1) apply_kernel(
    const float* __restrict__ x,
    const float* __restrict__ bias,
    float* __restrict__ out)
{
    extern __shared__ __align__(128) char sbuf[];
    __shared__ __align__(8) unsigned long long mbar[3];

    const int tid  = threadIdx.x;
    const int lane = tid & 31;
    const int row  = blockIdx.x * 2 + (tid >> 5);

    if (tid == 0) {
        mbar_init(s2u(&mbar[0]), 1);
        mbar_init(s2u(&mbar[1]), 1);
        mbar_init(s2u(&mbar[2]), 1);
    }

    ull L[4], U[4];
    {
        const float4* xl = reinterpret_cast<const float4*>(x + (size_t)row * N_WIRES + 8 * lane);
        const float4* xu = reinterpret_cast<const float4*>(x + (size_t)row * N_WIRES + 256 + 8 * lane);
        float4 a0 = xl[0], a1 = xl[1], b0 = xu[0], b1 = xu[1];
        L[0] = pk(a0.x, a1.x); L[1] = pk(a0.y, a1.y);
        L[2] = pk(a0.z, a1.z); L[3] = pk(a0.w, a1.w);
        U[0] = pk(b0.x, b1.x); U[1] = pk(b0.y, b1.y);
        U[2] = pk(b0.z, b1.z); U[3] = pk(b0.w, b1.w);
    }

    __syncthreads();

    if (tid == 0) {
        #pragma unroll
        for (int pc = 0; pc < 3; ++pc) {
            unsigned mb = s2u(&mbar[pc]);
            mbar_expect_tx(mb, CHUNK_B);
            bulk_g2s(s2u(sbuf) + pc * CHUNK_B, g_tab + (size_t)pc * CHUNK_B, CHUNK_B, mb);
        }
    }

    const unsigned sb = s2u(sbuf);
    unsigned rbase = sb + lane * 16;     // rot entries (per-chunk: += CHUNK_B, wrap)
    unsigned lbase = sb + lane * 8;      // left entries

    CoefH A0, A1, B0, B1;
    int rb = 0;
    #pragma unroll 1
    for (int c = 0; c < NCHUNK; ++c) {
        mbar_wait(s2u(&mbar[rb]), (unsigned)((c / 3) & 1));

        if (c >= MID_LO && c <= MID_HI) {
            LDH(A0, 0, 0); LDH(B0, 0, 1);
            LDH(A1, 1, 0); LDH(B1, 1, 1);  stage_both(L, U, A0, B0, lane);
            LDH(A0, 2, 0); LDH(B0, 2, 1);  stage_both(L, U, A1, B1, lane);
            LDH(A1, 3, 0); LDH(B1, 3, 1);  stage_both(L, U, A0, B0, lane);
            LDH(A0, 4, 0); LDH(B0, 4, 1);  stage_both(L, U, A1, B1, lane);
            LDH(A1, 5, 0); LDH(B1, 5, 1);  stage_both(L, U, A0, B0, lane);
            LDH(A0, 6, 0); LDH(B0, 6, 1);  stage_both(L, U, A1, B1, lane);
            LDH(A1, 7, 0); LDH(B1, 7, 1);  stage_both(L, U, A0, B0, lane);
            LDH(A0, 8, 0); LDH(B0, 8, 1);  stage_both(L, U, A1, B1, lane);
            LDH(A1, 9, 0); LDH(B1, 9, 1);  stage_both(L, U, A0, B0, lane);
            LDH(A0, 10, 0); LDH(B0, 10, 1); stage_both(L, U, A1, B1, lane);
            LDH(A1, 11, 0); LDH(B1, 11, 1); stage_both(L, U, A0, B0, lane);
            stage_both(L, U, A1, B1, lane);
        } else {
            LDH(A0, 0, 0);
            LDH(A1, 1, 0);   stage_lower(L, A0, lane);
            LDH(A0, 2, 0);   stage_lower(L, A1, lane);
            LDH(A1, 3, 0);   stage_lower(L, A0, lane);
            LDH(A0, 4, 0);   stage_lower(L, A1, lane);
            LDH(A1, 5, 0);   stage_lower(L, A0, lane);
            LDH(A0, 6, 0);   stage_lower(L, A1, lane);
            LDH(A1, 7, 0);   stage_lower(L, A0, lane);
            LDH(A0, 8, 0);   stage_lower(L, A1, lane);
            LDH(A1, 9, 0);   stage_lower(L, A0, lane);
            LDH(A0, 10, 0);  stage_lower(L, A1, lane);
            LDH(A1, 11, 0);  stage_lower(L, A0, lane);
            stage_lower(L, A1, lane);
        }

        __syncthreads();
        if (tid == 0 && c + 3 < NCHUNK) {
            fence_async_shared();
            unsigned mb = s2u(&mbar[rb]);
            mbar_expect_tx(mb, CHUNK_B);
            bulk_g2s(sb + rb * CHUNK_B, g_tab + (size_t)(c + 3) * CHUNK_B, CHUNK_B, mb);
        }

        rb = (rb == 2) ? 0 : rb + 1;
        rbase += CHUNK_B;
        lbase += CHUNK_B;
        if (rb == 0) { rbase -= 3 * CHUNK_B; lbase -= 3 * CHUNK_B; }
    }

    {
        const float* bl = bias + 8 * lane;
        float* ol = out + (size_t)row * N_WIRES + 8 * lane;
        float4 bb0 = *reinterpret_cast<const float4*>(bl);
        float4 bb1 = *reinterpret_cast<const float4*>(bl + 4);
        float4 bb2 = *reinterpret_cast<const float4*>(bl + 256);
        float4 bb3 = *reinterpret_cast<const float4*>(bl + 260);
        float4 o0, o1, o2, o3;
        o0.x = lo_f(L[0]) + bb0.x; o0.y = lo_f(L[1]) + bb0.y;
        o0.z = lo_f(L[2]) + bb0.z; o0.w = lo_f(L[3]) + bb0.w;
        o1.x = hi_f(L[0]) + bb1.x; o1.y = hi_f(L[1]) + bb1.y;
        o1.z = hi_f(L[2]) + bb1.z; o1.w = hi_f(L[3]) + bb1.w;
        o2.x = lo_f(U[0]) + bb2.x; o2.y = lo_f(U[1]) + bb2.y;
        o2.z = lo_f(U[2]) + bb2.z; o2.w = lo_f(U[3]) + bb2.w;
        o3.x = hi_f(U[0]) + bb3.x; o3.y = hi_f(U[1]) + bb3.y;
        o3.z = hi_f(U[2]) + bb3.z; o3.w = hi_f(U[3]) + bb3.w;
        *reinterpret_cast<float4*>(ol)       = o0;
        *reinterpret_cast<float4*>(ol + 4)   = o1;
        *reinterpret_cast<float4*>(ol + 256) = o2;
        *reinterpret_cast<float4*>(ol + 260) = o3;
    }
}

extern "C" void kernel_launch(void* const* d_in, const int* in_sizes, int n_in,
                              void* d_out, int out_size) {
    const float* x      = (const float*)d_in[0];
    const float* thetas = (const float*)d_in[1];
    const float* bias   = (const float*)d_in[2];
    float* out = (float*)d_out;

    build_cs_kernel<<<T_PAD, 128>>>(thetas);

    cudaFuncSetAttribute(apply_kernel,
                         cudaFuncAttributeMaxDynamicSharedMemorySize, 3 * CHUNK_B);

    int B = in_sizes[0] / N_WIRES;   // 256
    apply_kernel<<<B / 2, 64, 3 * CHUNK_B>>>(x, bias, out);
}

// round 13
// speedup vs baseline: 1.8624x; 1.1026x over previous
#include <cuda_runtime.h>

// Pyramid Givens circuit, n = m = 512, B = 256.
// Layer t in [0,1021): gates (i,i+1) for i ≡ t (mod 2), 0 <= i <= min(t, 1020-t).
// theta index: q=(t+i)/2, tidx = q(q+1)/2 + q - i.  Gate: a'=c*a+s*b ; b'=c*b-s*a.
//
// Lane L owns wires [8L,8L+7] (h=0) and [256+8L,256+8L+7] (h=1), packed as
// (v_{w+k}, v_{w+k+4}). Upper half active only for t in [255,765]; chunks
// (28 layers) phase-split into both-halves / lower-only straight-line bodies.
// All smem coefficient loads: 32-bit shared base + compile-time immediate.

#define N_WIRES   512
#define CHUNK_L   28
#define NCHUNK    37                   // 37*28 = 1036 layers (tail identity)
#define T_PAD     (NCHUNK * CHUNK_L)   // 1036
#define LAYER_B   2560                 // 128 rot double2 + 64 left float2
#define LEFT_OFF  2048
#define CHUNK_B   (CHUNK_L * LAYER_B)  // 71680
#define STAGE_B   (2 * LAYER_B)        // 5120
#define MID_LO    9                    // chunks 9..27 cover t in [252,783] ⊇ [255,765]
#define MID_HI    27

typedef unsigned long long ull;

__device__ __align__(128) char g_tab[(size_t)T_PAD * LAYER_B];   // ~2.65 MB

__device__ __forceinline__ float2 cs_of(const float* __restrict__ th, int t, int i) {
    if (t <= 1020 && i >= 0 && i <= t && i <= 1020 - t && (((i ^ t) & 1) == 0)) {
        int q = (t + i) >> 1;
        int tidx = (q * (q + 1)) / 2 + q - i;
        float s, c;
        __sincosf(th[tidx], &s, &c);    // |theta| <= pi: MUFU accuracy ~4e-7 abs
        return make_float2(c, s);
    }
    return make_float2(1.0f, 0.0f);
}

// 512 threads = 4 layers per block.
__global__ void build_cs_kernel(const float* __restrict__ thetas) {
    int t    = blockIdx.x * 4 + (threadIdx.x >> 7);
    if (t >= T_PAD) return;
    int h    = (threadIdx.x >> 6) & 1;
    int r    = (threadIdx.x >> 5) & 1;
    int lane = threadIdx.x & 31;
    int w    = 256 * h + 8 * lane;
    int ilo, ihi;
    if ((t & 1) == 0) { ilo = w + 2 * r;     ihi = ilo + 4; }
    else              { ilo = w + 2 * r + 1; ihi = ilo + 4; }
    float2 a = cs_of(thetas, t, ilo);
    float2 b = cs_of(thetas, t, ihi);
    char* base = g_tab + (size_t)t * LAYER_B;
    float2* dst = reinterpret_cast<float2*>(base + h * 1024 + r * 512 + lane * 16);
    dst[0] = make_float2(a.x, b.x);   // c2
    dst[1] = make_float2(a.y, b.y);   // s2
    if (r == 0) {
        float2 lf = cs_of(thetas, t, w - 1);
        *reinterpret_cast<float2*>(base + LEFT_OFF + (h * 32 + lane) * 8)
            = make_float2(lf.x, -lf.y);        // sine pre-negated
    }
}

// ---- f32x2 helpers ----
__device__ __forceinline__ ull mul2(ull a, ull b) {
    ull d; asm("mul.rn.f32x2 %0, %1, %2;" : "=l"(d) : "l"(a), "l"(b)); return d;
}
__device__ __forceinline__ ull fma2(ull a, ull b, ull c) {
    ull d; asm("fma.rn.f32x2 %0, %1, %2, %3;" : "=l"(d) : "l"(a), "l"(b), "l"(c)); return d;
}
__device__ __forceinline__ float lo_f(ull p) {
    float lo; asm("{ .reg .b32 hi_; mov.b64 {%0, hi_}, %1; }" : "=f"(lo) : "l"(p)); return lo;
}
__device__ __forceinline__ float hi_f(ull p) {
    float hi; asm("{ .reg .b32 lo_; mov.b64 {lo_, %0}, %1; }" : "=f"(hi) : "l"(p)); return hi;
}
__device__ __forceinline__ ull pk(float lo, float hi) {
    ull d; asm("mov.b64 %0, {%1, %2};" : "=l"(d) : "f"(lo), "f"(hi)); return d;
}

#define SGNMASK 0x8000000080000000ULL
#define FULLM   0xffffffffu

__device__ __forceinline__ void rotp2(ull& a, ull& b, ull c2, ull s2, ull ns2) {
    ull t1 = mul2(s2, b);
    ull na = fma2(c2, a, t1);
    ull t2 = mul2(ns2, a);
    b = fma2(c2, b, t2);
    a = na;
}

// ---- 32-bit shared loads with immediate offsets ----
template<int OFF>
__device__ __forceinline__ void lds_u64x2(unsigned base, ull& x, ull& y) {
    asm volatile("ld.shared.v2.u64 {%0, %1}, [%2+%3];"
                 : "=l"(x), "=l"(y) : "r"(base), "n"(OFF));
}
template<int OFF>
__device__ __forceinline__ void lds_f32x2(unsigned base, float& x, float& y) {
    asm volatile("ld.shared.v2.f32 {%0, %1}, [%2+%3];"
                 : "=f"(x), "=f"(y) : "r"(base), "n"(OFF));
}

// ---- bulk-copy / mbarrier helpers ----
__device__ __forceinline__ unsigned s2u(const void* p) {
    return (unsigned)__cvta_generic_to_shared(p);
}
__device__ __forceinline__ void mbar_init(unsigned mbar, unsigned cnt) {
    asm volatile("mbarrier.init.shared.b64 [%0], %1;" :: "r"(mbar), "r"(cnt) : "memory");
}
__device__ __forceinline__ void mbar_expect_tx(unsigned mbar, unsigned bytes) {
    asm volatile("mbarrier.arrive.expect_tx.shared.b64 _, [%0], %1;"
                 :: "r"(mbar), "r"(bytes) : "memory");
}
__device__ __forceinline__ void bulk_g2s(unsigned dst, const void* src, unsigned bytes,
                                         unsigned mbar) {
    asm volatile("cp.async.bulk.shared::cluster.global.mbarrier::complete_tx::bytes "
                 "[%0], [%1], %2, [%3];"
                 :: "r"(dst), "l"(src), "r"(bytes), "r"(mbar) : "memory");
}
__device__ __forceinline__ void mbar_wait(unsigned mbar, unsigned parity) {
    unsigned done;
    asm volatile(
        "{\n\t.reg .pred p;\n\t"
        "mbarrier.try_wait.parity.acquire.cta.shared::cta.b64 p, [%1], %2;\n\t"
        "selp.b32 %0, 1, 0, p;\n\t}"
        : "=r"(done) : "r"(mbar), "r"(parity) : "memory");
    if (!done) {
        asm volatile(
            "{\n\t.reg .pred P1;\n\t"
            "WL_%=:\n\t"
            "mbarrier.try_wait.parity.acquire.cta.shared::cta.b64 P1, [%0], %1, 0x989680;\n\t"
            "@P1 bra.uni WD_%=;\n\t"
            "bra.uni WL_%=;\n\t"
            "WD_%=:\n\t}"
            :: "r"(mbar), "r"(parity) : "memory");
    }
}
__device__ __forceinline__ void fence_async_shared() {
    asm volatile("fence.proxy.async.shared::cta;" ::: "memory");
}

struct CoefH {
    ull Ec0, Es0, Ec1, Es1;
    ull Oc0, Os0, Oc1, Os1;
    float lfc, lfs;     // lfs pre-negated
};

#define LDH(d, S, H) do {                                                        \
    lds_u64x2<(S)*STAGE_B + (H)*1024          >(rbase, (d).Ec0, (d).Es0);        \
    lds_u64x2<(S)*STAGE_B + (H)*1024 + 512    >(rbase, (d).Ec1, (d).Es1);        \
    lds_u64x2<(S)*STAGE_B + LAYER_B + (H)*1024      >(rbase, (d).Oc0, (d).Os0);  \
    lds_u64x2<(S)*STAGE_B + LAYER_B + (H)*1024 + 512>(rbase, (d).Oc1, (d).Os1);  \
    lds_f32x2<(S)*STAGE_B + LAYER_B + LEFT_OFF + (H)*256>(lbase, (d).lfc, (d).lfs); \
} while (0)

__device__ __forceinline__ void stage_lower(ull* L, CoefH& A, int lane) {
    ull nAs0 = A.Es0 ^ SGNMASK, nAs1 = A.Es1 ^ SGNMASK;
    ull nAo0 = A.Os0 ^ SGNMASK, nAo1 = A.Os1 ^ SGNMASK;
    rotp2(L[0], L[1], A.Ec0, A.Es0, nAs0);
    rotp2(L[2], L[3], A.Ec1, A.Es1, nAs1);
    float pl0  = lo_f(L[0]);
    float pl15 = hi_f(L[3]);
    float vnL = __shfl_down_sync(FULLM, pl0, 1);   // lane31 junk safe (identity gate)
    float lvL = __shfl_up_sync  (FULLM, pl15, 1);  // lane0 junk safe (identity left gate)
    float baseL = A.lfc * pl0;
    rotp2(L[1], L[2], A.Oc0, A.Os0, nAo0);
    ull Ql = pk(hi_f(L[0]), vnL);
    rotp2(L[3], Ql, A.Oc1, A.Os1, nAo1);
    float nv0 = fmaf(A.lfs, lvL, baseL);
    L[0] = pk(nv0, lo_f(Ql));
}

// Both-halves stage. Seam handled by index-mode wraparound shuffles:
// vnL: source y = (lane0 -> pu0, else pl0), read from lane+1 mod 32
//      -> lane31 gets pu0(0) = v256, others get v0(lane+1).
// lvU: source z = (lane31 -> pl15, else pu15), read from lane-1 mod 32
//      -> lane0 gets pl15(31) = v255, others get pu15(lane-1).
__device__ __forceinline__ void stage_both(ull* L, ull* U, CoefH& A, CoefH& Bc,
                                           int lane, int idxn, int idxp) {
    ull nAs0 = A.Es0 ^ SGNMASK, nAs1 = A.Es1 ^ SGNMASK;
    ull nAo0 = A.Os0 ^ SGNMASK, nAo1 = A.Os1 ^ SGNMASK;
    ull nBs0 = Bc.Es0 ^ SGNMASK, nBs1 = Bc.Es1 ^ SGNMASK;
    ull nBo0 = Bc.Os0 ^ SGNMASK, nBo1 = Bc.Os1 ^ SGNMASK;

    rotp2(L[0], L[1], A.Ec0, A.Es0, nAs0);
    rotp2(L[2], L[3], A.Ec1, A.Es1, nAs1);
    rotp2(U[0], U[1], Bc.Ec0, Bc.Es0, nBs0);
    rotp2(U[2], U[3], Bc.Ec1, Bc.Es1, nBs1);
    float pl0  = lo_f(L[0]);
    float pl15 = hi_f(L[3]);
    float pu0  = lo_f(U[0]);
    float pu15 = hi_f(U[3]);

    float y   = (lane == 0)  ? pu0  : pl0;
    float z   = (lane == 31) ? pl15 : pu15;
    float vnL = __shfl_sync(FULLM, y, idxn);
    float lvU = __shfl_sync(FULLM, z, idxp);
    float lvL = __shfl_up_sync  (FULLM, pl15, 1);  // lane0 junk safe
    float vnU = __shfl_down_sync(FULLM, pu0, 1);   // lane31 junk safe (511/512 identity)

    rotp2(L[1], L[2], A.Oc0, A.Os0, nAo0);
    ull Ql = pk(hi_f(L[0]), vnL);
    rotp2(L[3], Ql, A.Oc1, A.Os1, nAo1);
    float nv0 = fmaf(A.lfs, lvL, A.lfc * pl0);
    L[0] = pk(nv0, lo_f(Ql));

    rotp2(U[1], U[2], Bc.Oc0, Bc.Os0, nBo0);
    ull Qu = pk(hi_f(U[0]), vnU);
    rotp2(U[3], Qu, Bc.Oc1, Bc.Os1, nBo1);
    float nu0 = fmaf(Bc.lfs, lvU, Bc.lfc * pu0);
    U[0] = pk(nu0, lo_f(Qu));
}

__global__ void __launch_bounds__(64, 1) apply_kernel(
    const float* __restrict__ x,
    const float* __restrict__ bias,
    float* __restrict__ out)
{
    extern __shared__ __align__(128) char sbuf[];
    __shared__ __align__(8) unsigned long long mbar[3];

    const int tid  = threadIdx.x;
    const int lane = tid & 31;
    const int row  = blockIdx.x * 2 + (tid >> 5);
    const int idxn = (lane + 1) & 31;
    const int idxp = (lane - 1) & 31;

    if (tid == 0) {
        mbar_init(s2u(&mbar[0]), 1);
        mbar_init(s2u(&mbar[1]), 1);
        mbar_init(s2u(&mbar[2]), 1);
    }

    ull L[4], U[4];
    {
        const float4* xl = reinterpret_cast<const float4*>(x + (size_t)row * N_WIRES + 8 * lane);
        const float4* xu = reinterpret_cast<const float4*>(x + (size_t)row * N_WIRES + 256 + 8 * lane);
        float4 a0 = xl[0], a1 = xl[1], b0 = xu[0], b1 = xu[1];
        L[0] = pk(a0.x, a1.x); L[1] = pk(a0.y, a1.y);
        L[2] = pk(a0.z, a1.z); L[3] = pk(a0.w, a1.w);
        U[0] = pk(b0.x, b1.x); U[1] = pk(b0.y, b1.y);
        U[2] = pk(b0.z, b1.z); U[3] = pk(b0.w, b1.w);
    }

    __syncthreads();

    if (tid == 0) {
        #pragma unroll
        for (int pc = 0; pc < 3; ++pc) {
            unsigned mb = s2u(&mbar[pc]);
            mbar_expect_tx(mb, CHUNK_B);
            bulk_g2s(s2u(sbuf) + pc * CHUNK_B, g_tab + (size_t)pc * CHUNK_B, CHUNK_B, mb);
        }
    }

    const unsigned sb = s2u(sbuf);
    unsigned rbase = sb + lane * 16;
    unsigned lbase = sb + lane * 8;

    CoefH A0, A1, B0, B1;
    int rb = 0;
    #pragma unroll 1
    for (int c = 0; c < NCHUNK; ++c) {
        mbar_wait(s2u(&mbar[rb]), (unsigned)((c / 3) & 1));

        if (c >= MID_LO && c <= MID_HI) {
            LDH(A0, 0, 0);  LDH(B0, 0, 1);
            LDH(A1, 1, 0);  LDH(B1, 1, 1);   stage_both(L, U, A0, B0, lane, idxn, idxp);
            LDH(A0, 2, 0);  LDH(B0, 2, 1);   stage_both(L, U, A1, B1, lane, idxn, idxp);
            LDH(A1, 3, 0);  LDH(B1, 3, 1);   stage_both(L, U, A0, B0, lane, idxn, idxp);
            LDH(A0, 4, 0);  LDH(B0, 4, 1);   stage_both(L, U, A1, B1, lane, idxn, idxp);
            LDH(A1, 5, 0);  LDH(B1, 5, 1);   stage_both(L, U, A0, B0, lane, idxn, idxp);
            LDH(A0, 6, 0);  LDH(B0, 6, 1);   stage_both(L, U, A1, B1, lane, idxn, idxp);
            LDH(A1, 7, 0);  LDH(B1, 7, 1);   stage_both(L, U, A0, B0, lane, idxn, idxp);
            LDH(A0, 8, 0);  LDH(B0, 8, 1);   stage_both(L, U, A1, B1, lane, idxn, idxp);
            LDH(A1, 9, 0);  LDH(B1, 9, 1);   stage_both(L, U, A0, B0, lane, idxn, idxp);
            LDH(A0, 10, 0); LDH(B0, 10, 1);  stage_both(L, U, A1, B1, lane, idxn, idxp);
            LDH(A1, 11, 0); LDH(B1, 11, 1);  stage_both(L, U, A0, B0, lane, idxn, idxp);
            LDH(A0, 12, 0); LDH(B0, 12, 1);  stage_both(L, U, A1, B1, lane, idxn, idxp);
            LDH(A1, 13, 0); LDH(B1, 13, 1);  stage_both(L, U, A0, B0, lane, idxn, idxp);
            stage_both(L, U, A1, B1, lane, idxn, idxp);
        } else {
            LDH(A0, 0, 0);
            LDH(A1, 1, 0);   stage_lower(L, A0, lane);
            LDH(A0, 2, 0);   stage_lower(L, A1, lane);
            LDH(A1, 3, 0);   stage_lower(L, A0, lane);
            LDH(A0, 4, 0);   stage_lower(L, A1, lane);
            LDH(A1, 5, 0);   stage_lower(L, A0, lane);
            LDH(A0, 6, 0);   stage_lower(L, A1, lane);
            LDH(A1, 7, 0);   stage_lower(L, A0, lane);
            LDH(A0, 8, 0);   stage_lower(L, A1, lane);
            LDH(A1, 9, 0);   stage_lower(L, A0, lane);
            LDH(A0, 10, 0);  stage_lower(L, A1, lane);
            LDH(A1, 11, 0);  stage_lower(L, A0, lane);
            LDH(A0, 12, 0);  stage_lower(L, A1, lane);
            LDH(A1, 13, 0);  stage_lower(L, A0, lane);
            stage_lower(L, A1, lane);
        }

        __syncthreads();
        if (tid == 0 && c + 3 < NCHUNK) {
            fence_async_shared();
            unsigned mb = s2u(&mbar[rb]);
            mbar_expect_tx(mb, CHUNK_B);
            bulk_g2s(sb + rb * CHUNK_B, g_tab + (size_t)(c + 3) * CHUNK_B, CHUNK_B, mb);
        }

        rb = (rb == 2) ? 0 : rb + 1;
        rbase += CHUNK_B;
        lbase += CHUNK_B;
        if (rb == 0) { rbase -= 3 * CHUNK_B; lbase -= 3 * CHUNK_B; }
    }

    {
        const float* bl = bias + 8 * lane;
        float* ol = out + (size_t)row * N_WIRES + 8 * lane;
        float4 bb0 = *reinterpret_cast<const float4*>(bl);
        float4 bb1 = *reinterpret_cast<const float4*>(bl + 4);
        float4 bb2 = *reinterpret_cast<const float4*>(bl + 256);
        float4 bb3 = *reinterpret_cast<const float4*>(bl + 260);
        float4 o0, o1, o2, o3;
        o0.x = lo_f(L[0]) + bb0.x; o0.y = lo_f(L[1]) + bb0.y;
        o0.z = lo_f(L[2]) + bb0.z; o0.w = lo_f(L[3]) + bb0.w;
        o1.x = hi_f(L[0]) + bb1.x; o1.y = hi_f(L[1]) + bb1.y;
        o1.z = hi_f(L[2]) + bb1.z; o1.w = hi_f(L[3]) + bb1.w;
        o2.x = lo_f(U[0]) + bb2.x; o2.y = lo_f(U[1]) + bb2.y;
        o2.z = lo_f(U[2]) + bb2.z; o2.w = lo_f(U[3]) + bb2.w;
        o3.x = hi_f(U[0]) + bb3.x; o3.y = hi_f(U[1]) + bb3.y;
        o3.z = hi_f(U[2]) + bb3.z; o3.w = hi_f(U[3]) + bb3.w;
        *reinterpret_cast<float4*>(ol)       = o0;
        *reinterpret_cast<float4*>(ol + 4)   = o1;
        *reinterpret_cast<float4*>(ol + 256) = o2;
        *reinterpret_cast<float4*>(ol + 260) = o3;
    }
}

extern "C" void kernel_launch(void* const* d_in, const int* in_sizes, int n_in,
                              void* d_out, int out_size) {
    const float* x      = (const float*)d_in[0];
    const float* thetas = (const float*)d_in[1];
    const float* bias   = (const float*)d_in[2];
    float* out = (float*)d_out;

    build_cs_kernel<<<(T_PAD + 3) / 4, 512>>>(thetas);

    cudaFuncSetAttribute(apply_kernel,
                         cudaFuncAttributeMaxDynamicSharedMemorySize, 3 * CHUNK_B);

    int B = in_sizes[0] / N_WIRES;   // 256
    apply_kernel<<<B / 2, 64, 3 * CHUNK_B>>>(x, bias, out);
}